// round 5
// baseline (speedup 1.0000x reference)
#include <cuda_runtime.h>
#include <cuda_bf16.h>

#define LDIM 4096
#define BDIM 32
#define CIN  64
#define ODIM 128
#define KDIM 9
#define CCHUNKS 2               // split-K chunks over channel dim
#define CPER   (CIN / CCHUNKS)  // 32 channels per chunk
#define OCHUNK 64               // outputs per main-kernel block
#define WSTRIDE 10              // packed weight row: {w,w}x9, {bias,bias}

typedef unsigned long long u64;

// Scratch (allocation-free rule: __device__ globals)
__device__ float g_part[CCHUNKS * BDIM * LDIM];   // partial channel sums, 1 MB
__device__ float g_adj[BDIM * KDIM * LDIM];       // gathered+scaled adj, 4.7 MB
__device__ float g_wcn[ODIM * KDIM];              // normalized weight_coeff
__device__ float g_evinv;                         // 1 / ||err_vector||

// ---- packed f32x2 helpers (FFMA2 path) ----
__device__ __forceinline__ u64 pack2(float lo, float hi) {
    u64 r; asm("mov.b64 %0, {%1,%2};" : "=l"(r) : "f"(lo), "f"(hi)); return r;
}
__device__ __forceinline__ u64 ffma2(u64 a, u64 b, u64 c) {
    u64 d; asm("fma.rn.f32x2 %0, %1, %2, %3;" : "=l"(d) : "l"(a), "l"(b), "l"(c));
    return d;
}

// ---------------------------------------------------------------------------
// Kernel A: split-K channel reduction (512 blocks x 128 thr) + prep (block 512)
// ---------------------------------------------------------------------------
__global__ __launch_bounds__(128) void reduce_prep_kernel(
    const float* __restrict__ x,
    const float* __restrict__ wc,
    const float* __restrict__ ev) {

    const int bx = blockIdx.x;
    const int t  = threadIdx.x;

    if (bx < BDIM * 16) {                      // 512 reduce blocks
        const int b   = bx >> 4;               // 0..31
        const int sub = bx & 15;
        const int lt  = sub >> 1;              // l-tile 0..7 (128 float4 each)
        const int cc  = sub & 1;               // channel chunk 0..1
        const int l4  = lt * 128 + t;          // 0..1023

        const float4* xp = reinterpret_cast<const float4*>(x) +
                           ((size_t)b * CIN + cc * CPER) * (LDIM / 4) + l4;
        float4 a0 = make_float4(0.f, 0.f, 0.f, 0.f);
        float4 a1 = make_float4(0.f, 0.f, 0.f, 0.f);
#pragma unroll 8
        for (int i = 0; i < CPER; i += 2) {
            float4 v0 = __ldg(xp + (i    ) * (LDIM / 4));
            float4 v1 = __ldg(xp + (i + 1) * (LDIM / 4));
            a0.x += v0.x; a0.y += v0.y; a0.z += v0.z; a0.w += v0.w;
            a1.x += v1.x; a1.y += v1.y; a1.z += v1.z; a1.w += v1.w;
        }
        a0.x += a1.x; a0.y += a1.y; a0.z += a1.z; a0.w += a1.w;
        reinterpret_cast<float4*>(g_part)[(cc * BDIM + b) * (LDIM / 4) + l4] = a0;
        return;
    }

    // ---- prep block (128 threads) ----
    __shared__ float red[128];
    float ssq = 0.f;
    for (int i = t; i < LDIM; i += 128) { float v = ev[i]; ssq += v * v; }
    red[t] = ssq;
    __syncthreads();
    for (int s = 64; s > 0; s >>= 1) {
        if (t < s) red[t] += red[t + s];
        __syncthreads();
    }
    if (t == 0) g_evinv = rsqrtf(red[0]);

    // one thread per output channel (128 threads = ODIM)
    {
        float w[KDIM];
        float n = 0.f;
#pragma unroll
        for (int k = 0; k < KDIM; ++k) { w[k] = wc[t * KDIM + k]; n += w[k] * w[k]; }
        float inv = rsqrtf(n);
#pragma unroll
        for (int k = 0; k < KDIM; ++k) g_wcn[t * KDIM + k] = w[k] * inv;
    }
}

// ---------------------------------------------------------------------------
// Kernel B: adj[b,k,l] = (p0+p1)[b, idx[k,l]] * ev[l]/||ev||
// grid: (8 l-tiles of 512, 32 b) = 256 blocks x 128 thr. Gathers happen ONCE.
// ---------------------------------------------------------------------------
__global__ __launch_bounds__(128) void gather_kernel(
    const int*   __restrict__ idxm,
    const float* __restrict__ ev) {

    __shared__ float s_xs[LDIM];               // 16 KB

    const int tile = blockIdx.x;               // 0..7
    const int b    = blockIdx.y;               // 0..31
    const int t    = threadIdx.x;

    {   // stage xs[b] = p0 + p1 (L2-resident)
        float4* s4 = reinterpret_cast<float4*>(s_xs);
        const float4* g4 = reinterpret_cast<const float4*>(g_part);
#pragma unroll
        for (int i = t; i < LDIM / 4; i += 128) {
            float4 p0 = __ldg(&g4[(0 * BDIM + b) * (LDIM / 4) + i]);
            float4 p1 = __ldg(&g4[(1 * BDIM + b) * (LDIM / 4) + i]);
            s4[i] = make_float4(p0.x + p1.x, p0.y + p1.y,
                                p0.z + p1.z, p0.w + p1.w);
        }
    }
    __syncthreads();

    const int l = tile * 512 + t * 4;
    const float evinv = g_evinv;
    float4 e4 = __ldg(reinterpret_cast<const float4*>(ev + l));
    const float ex = e4.x * evinv, ey = e4.y * evinv,
                ez = e4.z * evinv, ew = e4.w * evinv;

#pragma unroll
    for (int k = 0; k < KDIM; ++k) {
        int4 id = __ldg(reinterpret_cast<const int4*>(idxm + k * LDIM + l));
        float4 r = make_float4(s_xs[id.x] * ex, s_xs[id.y] * ey,
                               s_xs[id.z] * ez, s_xs[id.w] * ew);
        *reinterpret_cast<float4*>(&g_adj[((size_t)b * KDIM + k) * LDIM + l]) = r;
    }
}

// ---------------------------------------------------------------------------
// Kernel C: out[b,o,l] = sum_k wcn[o,k] * adj[b,k,l] + bias[o]
// grid: (16 l-tiles of 256, 32 b, 2 o-chunks of 64) = 1024 blocks x 128 thr.
// Each thread owns one f32x2 pair of l; pure FFMA2 inner loop.
// ---------------------------------------------------------------------------
__global__ __launch_bounds__(128) void gmconv_main_kernel(
    const float* __restrict__ bias,
    float*       __restrict__ out) {

    __shared__ u64 s_wp[OCHUNK * WSTRIDE];     // {w,w}x9 + {bias,bias}; 5 KB

    const int tile  = blockIdx.x;              // 0..15
    const int b     = blockIdx.y;              // 0..31
    const int obase = blockIdx.z * OCHUNK;     // 0, 64
    const int t     = threadIdx.x;

    // stage packed weights + bias
    for (int i = t; i < OCHUNK * WSTRIDE; i += 128) {
        int o = i / WSTRIDE, s = i - o * WSTRIDE;
        float w = (s < KDIM) ? g_wcn[(obase + o) * KDIM + s] : bias[obase + o];
        s_wp[i] = pack2(w, w);
    }
    __syncthreads();

    const int l = tile * 256 + t * 2;

    // load 9 adj pairs (coalesced, L2-resident)
    u64 a[KDIM];
#pragma unroll
    for (int k = 0; k < KDIM; ++k)
        a[k] = *reinterpret_cast<const u64*>(&g_adj[((size_t)b * KDIM + k) * LDIM + l]);

    float* outp = out + ((size_t)b * ODIM + obase) * LDIM + l;
#pragma unroll 4
    for (int o = 0; o < OCHUNK; ++o) {
        const u64* wp = &s_wp[o * WSTRIDE];
        u64 acc = wp[KDIM];                    // {bias,bias}
#pragma unroll
        for (int k = 0; k < KDIM; ++k)
            acc = ffma2(wp[k], a[k], acc);
        *reinterpret_cast<u64*>(outp + (size_t)o * LDIM) = acc;   // STG.64
    }
}

// ---------------------------------------------------------------------------
extern "C" void kernel_launch(void* const* d_in, const int* in_sizes, int n_in,
                              void* d_out, int out_size) {
    const float* x    = nullptr;
    const float* wc   = nullptr;
    const float* ev   = nullptr;
    const float* bias = nullptr;
    const int*   idxm = nullptr;

    for (int i = 0; i < n_in; ++i) {
        switch (in_sizes[i]) {
            case BDIM * CIN * LDIM: x    = (const float*)d_in[i]; break;  // 8388608
            case ODIM * KDIM:       wc   = (const float*)d_in[i]; break;  // 1152
            case LDIM:              ev   = (const float*)d_in[i]; break;  // 4096
            case ODIM:              bias = (const float*)d_in[i]; break;  // 128
            case KDIM * LDIM:       idxm = (const int*)  d_in[i]; break;  // 36864
            default: break;
        }
    }

    float* out = (float*)d_out;

    reduce_prep_kernel<<<BDIM * 16 + 1, 128>>>(x, wc, ev);
    gather_kernel<<<dim3(8, BDIM), 128>>>(idxm, ev);
    gmconv_main_kernel<<<dim3(16, BDIM, 2), 128>>>(bias, out);
}